// round 7
// baseline (speedup 1.0000x reference)
#include <cuda_runtime.h>
#include <cuda_bf16.h>

// Blur_by_Kernel: per-batch 21x21 cross-correlation, reflect pad 10.
// out[b,c,y,x] = sum_{i,j} in_reflect[b,c, y+i-10, x+j-10] * ker[b,i,j]
// B=16, C=3, H=W=768, K=21.
//
// j-paired f32x2 formulation (no odd-pair packs):
//   even out x=xb+2q:   Sum_m pe[q+m] . ke[m],  ke[m] = (k[2m], k[2m+1]) (k[21]=0)
//   odd  out x=xb+2q+1: Sum_m pe[q+m] . ko[m],  ko[m] = (k[2m-1], k[2m]) (k[-1]=0)
// pe[p] = aligned pair (w[xb+2p], w[xb+2p+1]); horizontal lo+hi at the end.
//
// RF-bank note: FFMA2 with 3 distinct 64b operands issues at rt=3 (bank reads).
// The inner loops are blocked so 8 consecutive FFMA2 share the SAME multiplier
// register pair -> ptxas .reuse on the b port -> rt=2 for 7 of 8.

static const int H = 768;
static const int W = 768;
static const int KS = 21;
static const int PAD = 10;

static const int TX = 128;          // output tile width
static const int TY = 64;           // output tile height
static const int SROWS = TY + 20;   // 84 smem rows
static const int SCOLS = TX + 20;   // 148 valid smem cols
static const int SSTRIDE = 152;     // padded row stride (floats), 608 B
static const int KROW_F2 = 22;      // kernel row: 11 interleaved (ke, ko) float2
static const int KROW_BYTES = KROW_F2 * 8;   // 176

static const int SMEM_IN_BYTES = SROWS * SSTRIDE * 4;             // 51072
static const int SMEM_K_OFF    = SMEM_IN_BYTES;
static const int SMEM_TOTAL    = SMEM_IN_BYTES + KS * KROW_BYTES; // 54768

typedef unsigned long long ull;

// 16B-preserving swizzle: XOR bits[4:5] with bits[7:8]. Conflict-free LDS.128
// for the 64B lane stride below.
__device__ __forceinline__ int swz2(int a) { return a ^ ((a >> 3) & 0x30); }

// volatile: pin relative order so same-multiplier blocks stay contiguous
// (enables the operand-reuse latch on the b port).
__device__ __forceinline__ void ffma2(ull a, ull b, ull& c) {
    asm volatile("fma.rn.f32x2 %0, %1, %2, %0;" : "+l"(c) : "l"(a), "l"(b));
}

__device__ __forceinline__ float2 upk(ull v) {
    float2 r;
    asm("mov.b64 {%0, %1}, %2;" : "=f"(r.x), "=f"(r.y) : "l"(v));
    return r;
}

__device__ __forceinline__ int refl(int i, int n) {
    i = (i < 0) ? -i : i;
    if (i >= n) i = 2 * n - 2 - i;
    return i;
}

__global__ __launch_bounds__(256, 2)
void blur_kernel(const float* __restrict__ in,
                 const float* __restrict__ ker,
                 float* __restrict__ out)
{
    extern __shared__ __align__(128) char smem[];
    float*  s_in = (float*)smem;
    float2* s_kp = (float2*)(smem + SMEM_K_OFF);

    const int tid   = threadIdx.x;
    const int plane = blockIdx.z;          // b*3 + c
    const int b     = plane / 3;
    const int X0    = blockIdx.x * TX;
    const int Y0    = blockIdx.y * TY;

    // ---- kernel pairs: per row i, interleaved ke[m], ko[m] (m=0..10) ----
    {
        const float* kb = ker + b * (KS * KS);
        for (int t = tid; t < KS * 11; t += 256) {
            int i = t / 11, m = t - i * 11;
            const float* kr = kb + i * KS;
            float k2m   = kr[2 * m];
            float k2m1  = (2 * m + 1 < KS) ? kr[2 * m + 1] : 0.0f;
            float k2mm1 = (m > 0) ? kr[2 * m - 1] : 0.0f;
            float2* row = s_kp + i * KROW_F2;
            row[2 * m]     = make_float2(k2m, k2m1);    // ke[m]
            row[2 * m + 1] = make_float2(k2mm1, k2m);   // ko[m]
        }
    }

    // ---- input tile with reflect padding, swizzled store ----
    {
        const float* pin = in + (long long)plane * H * W;
        const int NLOAD = SROWS * SCOLS;  // 12432
        char* sb = (char*)s_in;
        for (int idx = tid; idx < NLOAD; idx += 256) {
            int ry = idx / SCOLS;
            int rx = idx - ry * SCOLS;
            int gy = refl(Y0 - PAD + ry, H);
            int gx = refl(X0 - PAD + rx, W);
            *(float*)(sb + swz2((ry * SSTRIDE + rx) * 4)) = pin[gy * W + gx];
        }
    }
    __syncthreads();

    // ---- compute: 16(x) x 2(y) outputs/thread, slide over INPUT rows ----
    const int tx = tid & 7;       // x offset tx*16
    const int ty = tid >> 3;      // y offset ty*2 (0..31)
    const int xb = tx * 16;

    ull accE0[8] = {0, 0, 0, 0, 0, 0, 0, 0};  // row 0, even outputs
    ull accO0[8] = {0, 0, 0, 0, 0, 0, 0, 0};  // row 0, odd outputs
    ull accE1[8] = {0, 0, 0, 0, 0, 0, 0, 0};  // row 1
    ull accO1[8] = {0, 0, 0, 0, 0, 0, 0, 0};

    const char* sb = (const char*)s_in;
    int lrow = ((ty * 2) * SSTRIDE + xb) * 4;   // byte offset of window start

#pragma unroll 1
    for (int u = 0; u <= 21; ++u) {
        // window: 36 floats = 9 aligned 16B loads (swizzled, conflict-free),
        // loaded directly as ull pairs (no repack MOVs)
        ull pe[18];
#pragma unroll
        for (int t = 0; t < 9; ++t) {
            ulonglong2 v = *(const ulonglong2*)(sb + swz2(lrow + t * 16));
            pe[2 * t]     = v.x;
            pe[2 * t + 1] = v.y;
        }

        // input row (ty*2+u) feeds: out row 0 with kernel row u, row 1 with u-1
        if (u < 21) {
            const ulonglong2* kr =
                (const ulonglong2*)((const char*)s_kp + u * KROW_BYTES);
#pragma unroll
            for (int m = 0; m < 11; ++m) {
                ulonglong2 kd = kr[m];   // (ke[m], ko[m]) broadcast LDS.128
                // 8-blocks sharing one multiplier -> b-port .reuse, rt~2
#pragma unroll
                for (int q = 0; q < 8; ++q) ffma2(pe[q + m], kd.x, accE0[q]);
#pragma unroll
                for (int q = 0; q < 8; ++q) ffma2(pe[q + m], kd.y, accO0[q]);
            }
        }
        if (u > 0) {
            const ulonglong2* kr =
                (const ulonglong2*)((const char*)s_kp + (u - 1) * KROW_BYTES);
#pragma unroll
            for (int m = 0; m < 11; ++m) {
                ulonglong2 kd = kr[m];
#pragma unroll
                for (int q = 0; q < 8; ++q) ffma2(pe[q + m], kd.x, accE1[q]);
#pragma unroll
                for (int q = 0; q < 8; ++q) ffma2(pe[q + m], kd.y, accO1[q]);
            }
        }
        lrow += SSTRIDE * 4;
    }

    // ---- horizontal reduce + store (float4 = 2 even/odd output pairs) ----
    float* pout = out + (long long)plane * H * W;
    {
        int y0 = Y0 + ty * 2;
        float4* row0 = (float4*)&pout[(long long)y0 * W + X0 + xb];
        float4* row1 = (float4*)&pout[(long long)(y0 + 1) * W + X0 + xb];
#pragma unroll
        for (int q2 = 0; q2 < 4; ++q2) {
            float2 e0 = upk(accE0[2 * q2]),     o0 = upk(accO0[2 * q2]);
            float2 e1 = upk(accE0[2 * q2 + 1]), o1 = upk(accO0[2 * q2 + 1]);
            row0[q2] = make_float4(e0.x + e0.y, o0.x + o0.y,
                                   e1.x + e1.y, o1.x + o1.y);
        }
#pragma unroll
        for (int q2 = 0; q2 < 4; ++q2) {
            float2 e0 = upk(accE1[2 * q2]),     o0 = upk(accO1[2 * q2]);
            float2 e1 = upk(accE1[2 * q2 + 1]), o1 = upk(accO1[2 * q2 + 1]);
            row1[q2] = make_float4(e0.x + e0.y, o0.x + o0.y,
                                   e1.x + e1.y, o1.x + o1.y);
        }
    }
}

extern "C" void kernel_launch(void* const* d_in, const int* in_sizes, int n_in,
                              void* d_out, int out_size)
{
    const float* in  = (const float*)d_in[0];   // (16,3,768,768)
    const float* ker = (const float*)d_in[1];   // (16,21,21)
    float* out = (float*)d_out;

    static int smem_set = 0;
    if (!smem_set) {
        cudaFuncSetAttribute(blur_kernel,
                             cudaFuncAttributeMaxDynamicSharedMemorySize,
                             SMEM_TOTAL);
        smem_set = 1;
    }

    dim3 grid(W / TX, H / TY, 16 * 3);  // (6, 12, 48)
    dim3 block(256);
    blur_kernel<<<grid, block, SMEM_TOTAL>>>(in, ker, out);
}

// round 8
// speedup vs baseline: 1.4250x; 1.4250x over previous
#include <cuda_runtime.h>
#include <cuda_bf16.h>

// Blur_by_Kernel: per-batch 21x21 cross-correlation, reflect pad 10.
// out[b,c,y,x] = sum_{i,j} in_reflect[b,c, y+i-10, x+j-10] * ker[b,i,j]
// B=16, C=3, H=W=768, K=21.
//
// j-paired f32x2 formulation (no odd-pair packs):
//   even out x=xb+2q:   Sum_m pe[q+m] . ke[m],  ke[m] = (k[2m], k[2m+1]) (k[21]=0)
//   odd  out x=xb+2q+1: Sum_m pe[q+m] . ko[m],  ko[m] = (k[2m-1], k[2m]) (k[-1]=0)
// pe[p] = aligned pair (w[xb+2p], w[xb+2p+1]); horizontal lo+hi at the end.
//
// One output row per thread (16 outputs), 3 CTAs/SM for latency coverage.
// Inner loop kept in the R6 interleaved non-volatile form (rt~2 via reuse).

static const int H = 768;
static const int W = 768;
static const int KS = 21;
static const int PAD = 10;

static const int TX = 128;          // output tile width
static const int TY = 32;           // output tile height (1 row/thread)
static const int SROWS = TY + 20;   // 52 smem rows
static const int SCOLS = TX + 20;   // 148 valid smem cols
static const int SSTRIDE = 152;     // padded row stride (floats), 608 B
static const int KROW_F2 = 22;      // kernel row: 11 interleaved (ke, ko) float2
static const int KROW_BYTES = KROW_F2 * 8;   // 176

typedef unsigned long long ull;

// 16B-preserving swizzle: XOR bits[4:5] with bits[7:8]. Conflict-free LDS.128
// for the 64B lane stride below.
__device__ __forceinline__ int swz2(int a) { return a ^ ((a >> 3) & 0x30); }

__device__ __forceinline__ void ffma2(ull a, ull b, ull& c) {
    asm("fma.rn.f32x2 %0, %1, %2, %0;" : "+l"(c) : "l"(a), "l"(b));
}

__device__ __forceinline__ float2 upk(ull v) {
    float2 r;
    asm("mov.b64 {%0, %1}, %2;" : "=f"(r.x), "=f"(r.y) : "l"(v));
    return r;
}

__device__ __forceinline__ int refl(int i, int n) {
    i = (i < 0) ? -i : i;
    if (i >= n) i = 2 * n - 2 - i;
    return i;
}

__global__ __launch_bounds__(256, 3)
void blur_kernel(const float* __restrict__ in,
                 const float* __restrict__ ker,
                 float* __restrict__ out)
{
    __shared__ __align__(128) float  s_in[SROWS * SSTRIDE]; // 31616 B
    __shared__ __align__(16)  float2 s_kp[KS * KROW_F2];    //  3696 B

    const int tid   = threadIdx.x;
    const int plane = blockIdx.z;          // b*3 + c
    const int b     = plane / 3;
    const int X0    = blockIdx.x * TX;
    const int Y0    = blockIdx.y * TY;

    // ---- kernel pairs: per row i, interleaved ke[m], ko[m] (m=0..10) ----
    {
        const float* kb = ker + b * (KS * KS);
        for (int t = tid; t < KS * 11; t += 256) {
            int i = t / 11, m = t - i * 11;
            const float* kr = kb + i * KS;
            float k2m   = kr[2 * m];
            float k2m1  = (2 * m + 1 < KS) ? kr[2 * m + 1] : 0.0f;
            float k2mm1 = (m > 0) ? kr[2 * m - 1] : 0.0f;
            float2* row = s_kp + i * KROW_F2;
            row[2 * m]     = make_float2(k2m, k2m1);    // ke[m]
            row[2 * m + 1] = make_float2(k2mm1, k2m);   // ko[m]
        }
    }

    // ---- input tile with reflect padding, swizzled store ----
    {
        const float* pin = in + (long long)plane * H * W;
        const int NLOAD = SROWS * SCOLS;  // 7696
        char* sb = (char*)s_in;
        for (int idx = tid; idx < NLOAD; idx += 256) {
            int ry = idx / SCOLS;
            int rx = idx - ry * SCOLS;
            int gy = refl(Y0 - PAD + ry, H);
            int gx = refl(X0 - PAD + rx, W);
            *(float*)(sb + swz2((ry * SSTRIDE + rx) * 4)) = pin[gy * W + gx];
        }
    }
    __syncthreads();

    // ---- compute: 16 outputs/thread on ONE row, slide over 21 input rows ----
    const int tx = tid & 7;       // x offset tx*16
    const int ty = tid >> 3;      // output row ty (0..31)
    const int xb = tx * 16;

    ull accE[8] = {0, 0, 0, 0, 0, 0, 0, 0};  // even outputs
    ull accO[8] = {0, 0, 0, 0, 0, 0, 0, 0};  // odd outputs

    const char* sb = (const char*)s_in;
    int lrow = (ty * SSTRIDE + xb) * 4;      // byte offset of window start

#pragma unroll 1
    for (int u = 0; u < 21; ++u) {
        // window: 36 floats = 9 aligned 16B loads (swizzled, conflict-free)
        ull pe[18];
#pragma unroll
        for (int t = 0; t < 9; ++t) {
            ulonglong2 v = *(const ulonglong2*)(sb + swz2(lrow + t * 16));
            pe[2 * t]     = v.x;
            pe[2 * t + 1] = v.y;
        }

        const ulonglong2* kr =
            (const ulonglong2*)((const char*)s_kp + u * KROW_BYTES);
#pragma unroll
        for (int m = 0; m < 11; ++m) {
            ulonglong2 kd = kr[m];   // (ke[m], ko[m]) broadcast LDS.128
#pragma unroll
            for (int q = 0; q < 8; ++q) {
                ffma2(pe[q + m], kd.x, accE[q]);   // consecutive pair shares
                ffma2(pe[q + m], kd.y, accO[q]);   // a-operand -> reuse, rt~2
            }
        }
        lrow += SSTRIDE * 4;
    }

    // ---- horizontal reduce + store (float4 = 2 even/odd output pairs) ----
    float* pout = out + (long long)plane * H * W;
    {
        int y = Y0 + ty;
        float4* row = (float4*)&pout[(long long)y * W + X0 + xb];
#pragma unroll
        for (int q2 = 0; q2 < 4; ++q2) {
            float2 e0 = upk(accE[2 * q2]),     o0 = upk(accO[2 * q2]);
            float2 e1 = upk(accE[2 * q2 + 1]), o1 = upk(accO[2 * q2 + 1]);
            row[q2] = make_float4(e0.x + e0.y, o0.x + o0.y,
                                  e1.x + e1.y, o1.x + o1.y);
        }
    }
}

extern "C" void kernel_launch(void* const* d_in, const int* in_sizes, int n_in,
                              void* d_out, int out_size)
{
    const float* in  = (const float*)d_in[0];   // (16,3,768,768)
    const float* ker = (const float*)d_in[1];   // (16,21,21)
    float* out = (float*)d_out;

    dim3 grid(W / TX, H / TY, 16 * 3);  // (6, 24, 48)
    dim3 block(256);
    blur_kernel<<<grid, block>>>(in, ker, out);
}